// round 1
// baseline (speedup 1.0000x reference)
#include <cuda_runtime.h>
#include <math.h>

// ---------------------------------------------------------------------------
// GCN_trad: two GCN branches (4 layers each) + global-average-pool + MLP.
// Round 0: correct fp32 baseline.
//   - gcn_conv rewritten as relu((A_hat h) W + b); A_hat (dinv) precomputed once.
//   - edge aggregation with vector f32 reductions (red.global.add.v4.f32).
//   - register-tiled fp32 SGEMM (BM=64, BN=128, BK=16, 8x8 per thread).
// ---------------------------------------------------------------------------

#define NLMAX 100000
#define NSMAX 50000
#define NG    512

__device__ __align__(256) float g_z_l[(size_t)NLMAX * 128];
__device__ __align__(256) float g_h_l[(size_t)NLMAX * 128];
__device__ __align__(256) float g_z_s[(size_t)NSMAX * 128];
__device__ __align__(256) float g_h_s[(size_t)NSMAX * 128];
__device__ __align__(256) float g_dinv_l[NLMAX];
__device__ __align__(256) float g_dinv_s[NSMAX];
__device__ __align__(256) float g_pool[NG * 128];
__device__ __align__(256) float g_cnt[NG];
__device__ __align__(256) float g_m1[NG * 128];

// ---------------------------------------------------------------------------

__global__ void zero_f(float* __restrict__ p, int n) {
    int i = blockIdx.x * blockDim.x + threadIdx.x;
    if (i < n) p[i] = 0.f;
}

__global__ void deg_accum(const int* __restrict__ dst, const float* __restrict__ w,
                          float* __restrict__ deg, int E) {
    int e = blockIdx.x * blockDim.x + threadIdx.x;
    if (e < E) atomicAdd(&deg[dst[e]], w[e]);
}

__global__ void finish_dinv(float* __restrict__ d, int n) {
    int i = blockIdx.x * blockDim.x + threadIdx.x;
    if (i < n) d[i] = rsqrtf(1.0f + d[i]);
}

// z = dinv^2 * h   (elementwise, self-loop term of A_hat)
__global__ void init_z(const float* __restrict__ h, const float* __restrict__ dinv,
                       float* __restrict__ z, int total, int shift) {
    int i = blockIdx.x * blockDim.x + threadIdx.x;
    if (i < total) {
        float di = dinv[i >> shift];
        z[i] = di * di * h[i];
    }
}

// z[dst] += (w * dinv[src] * dinv[dst]) * h[src], one float4 per thread
template <int C4>
__global__ void agg_edges(const float4* __restrict__ h4, const int* __restrict__ src,
                          const int* __restrict__ dst, const float* __restrict__ w,
                          const float* __restrict__ dinv, float* __restrict__ z,
                          long long total) {
    long long idx = (long long)blockIdx.x * blockDim.x + threadIdx.x;
    if (idx >= total) return;
    int e = (int)(idx / C4);
    int c = (int)(idx % C4);
    int s = __ldg(&src[e]);
    int d = __ldg(&dst[e]);
    float nrm = __ldg(&w[e]) * __ldg(&dinv[s]) * __ldg(&dinv[d]);
    float4 v = h4[(size_t)s * C4 + c];
    float* p = z + ((size_t)d * C4 + c) * 4;
    asm volatile("red.global.add.v4.f32 [%0], {%1,%2,%3,%4};"
                 :: "l"(p), "f"(v.x * nrm), "f"(v.y * nrm),
                    "f"(v.z * nrm), "f"(v.w * nrm)
                 : "memory");
}

// H = relu(Z @ W + bias), Z:[N,K], W:[K,128], H:[N,128]
template <int K>
__global__ __launch_bounds__(128) void gemm_bias_relu(
    const float* __restrict__ Z, const float* __restrict__ W,
    const float* __restrict__ bias, float* __restrict__ H, int N) {
    const int BM = 64, BK = 16;
    __shared__ __align__(16) float Zs[BK][BM];
    __shared__ __align__(16) float Ws[BK][128];

    int tid = threadIdx.x;
    int row0 = blockIdx.x * BM;
    int tx = tid & 15;   // 16 column groups of 8
    int ty = tid >> 4;   // 8 row groups of 8

    float acc[8][8];
#pragma unroll
    for (int i = 0; i < 8; i++)
#pragma unroll
        for (int j = 0; j < 8; j++) acc[i][j] = 0.f;

    int zr = tid >> 1;
    int zc = (tid & 1) * 8;
    int wcol = (tid & 31) * 4;
    int wrow0 = tid >> 5;  // 0..3

    for (int k0 = 0; k0 < K; k0 += BK) {
        float4 a0 = make_float4(0.f, 0.f, 0.f, 0.f), a1 = a0;
        int grow = row0 + zr;
        if (grow < N) {
            const float4* zp = (const float4*)(Z + (size_t)grow * K + k0 + zc);
            a0 = zp[0];
            a1 = zp[1];
        }
        Zs[zc + 0][zr] = a0.x; Zs[zc + 1][zr] = a0.y;
        Zs[zc + 2][zr] = a0.z; Zs[zc + 3][zr] = a0.w;
        Zs[zc + 4][zr] = a1.x; Zs[zc + 5][zr] = a1.y;
        Zs[zc + 6][zr] = a1.z; Zs[zc + 7][zr] = a1.w;
#pragma unroll
        for (int p = 0; p < 4; p++) {
            int wr = p * 4 + wrow0;
            *(float4*)&Ws[wr][wcol] = *(const float4*)(W + (size_t)(k0 + wr) * 128 + wcol);
        }
        __syncthreads();
#pragma unroll
        for (int k = 0; k < BK; k++) {
            float a[8], b[8];
            *(float4*)&a[0] = *(const float4*)&Zs[k][ty * 8];
            *(float4*)&a[4] = *(const float4*)&Zs[k][ty * 8 + 4];
            *(float4*)&b[0] = *(const float4*)&Ws[k][tx * 8];
            *(float4*)&b[4] = *(const float4*)&Ws[k][tx * 8 + 4];
#pragma unroll
            for (int i = 0; i < 8; i++)
#pragma unroll
                for (int j = 0; j < 8; j++) acc[i][j] += a[i] * b[j];
        }
        __syncthreads();
    }

    float bv[8];
    *(float4*)&bv[0] = *(const float4*)&bias[tx * 8];
    *(float4*)&bv[4] = *(const float4*)&bias[tx * 8 + 4];
#pragma unroll
    for (int i = 0; i < 8; i++) {
        int r = row0 + ty * 8 + i;
        if (r < N) {
            float4 o0, o1;
            o0.x = fmaxf(acc[i][0] + bv[0], 0.f);
            o0.y = fmaxf(acc[i][1] + bv[1], 0.f);
            o0.z = fmaxf(acc[i][2] + bv[2], 0.f);
            o0.w = fmaxf(acc[i][3] + bv[3], 0.f);
            o1.x = fmaxf(acc[i][4] + bv[4], 0.f);
            o1.y = fmaxf(acc[i][5] + bv[5], 0.f);
            o1.z = fmaxf(acc[i][6] + bv[6], 0.f);
            o1.w = fmaxf(acc[i][7] + bv[7], 0.f);
            *(float4*)(H + (size_t)r * 128 + tx * 8) = o0;
            *(float4*)(H + (size_t)r * 128 + tx * 8 + 4) = o1;
        }
    }
}

// pool[batch[i]] += h[i] ; cnt[batch[i]] += 1
__global__ void pool_accum(const float4* __restrict__ h4, const int* __restrict__ batch,
                           float* __restrict__ pool, float* __restrict__ cnt, int N) {
    int idx = blockIdx.x * blockDim.x + threadIdx.x;
    int i = idx >> 5;
    int c = idx & 31;
    if (i >= N) return;
    int b = __ldg(&batch[i]);
    float4 v = h4[(size_t)i * 32 + c];
    float* p = pool + (size_t)b * 128 + c * 4;
    asm volatile("red.global.add.v4.f32 [%0], {%1,%2,%3,%4};"
                 :: "l"(p), "f"(v.x), "f"(v.y), "f"(v.z), "f"(v.w)
                 : "memory");
    if (c == 0) atomicAdd(&cnt[b], 1.0f);
}

// m1[g] = (pool[g]/max(cnt,1)) @ lin1_W + lin1_b   (one block per graph, 128 thr)
__global__ void mlp1(const float* __restrict__ pool, const float* __restrict__ cnt,
                     const float* __restrict__ W, const float* __restrict__ b,
                     float* __restrict__ out) {
    __shared__ float p[128];
    int g = blockIdx.x, j = threadIdx.x;
    float c = cnt[g];
    c = (c < 1.f) ? 1.f : c;
    p[j] = pool[(size_t)g * 128 + j] / c;
    __syncthreads();
    float acc = b[j];
#pragma unroll
    for (int k = 0; k < 128; k++) acc += p[k] * W[(size_t)k * 128 + j];
    out[(size_t)g * 128 + j] = acc;
}

// h2 = BN(relu? no: BN then relu)(m1 @ lin2_W + lin2_b); out = h2 @ out_W + out_b
__global__ void mlp2(const float* __restrict__ m1, const float* __restrict__ W2,
                     const float* __restrict__ b2, const float* __restrict__ gamma,
                     const float* __restrict__ beta, const float* __restrict__ outW,
                     const float* __restrict__ outb, float* __restrict__ dout) {
    __shared__ float p[128];
    __shared__ float hred[64];
    int g = blockIdx.x, j = threadIdx.x;  // 64 threads
    p[j] = m1[(size_t)g * 128 + j];
    p[j + 64] = m1[(size_t)g * 128 + 64 + j];
    __syncthreads();
    float acc = b2[j];
#pragma unroll
    for (int k = 0; k < 128; k++) acc += p[k] * W2[(size_t)k * 64 + j];
    // eval BatchNorm: running mean 0, var 1
    float h = acc * rsqrtf(1.0f + 1e-5f) * gamma[j] + beta[j];
    h = fmaxf(h, 0.f);
    dout[NG + (size_t)g * 64 + j] = h;  // second output (h), after first (out)
    hred[j] = h * outW[j];
    __syncthreads();
#pragma unroll
    for (int off = 32; off >= 1; off >>= 1) {
        if (j < off) hred[j] += hred[j + off];
        __syncthreads();
    }
    if (j == 0) dout[g] = hred[0] + outb[0];
}

// ---------------------------------------------------------------------------

static inline int cdiv(long long n, int t) { return (int)((n + t - 1) / t); }

extern "C" void kernel_launch(void* const* d_in, const int* in_sizes, int n_in,
                              void* d_out, int out_size) {
    const float* x_l     = (const float*)d_in[0];
    const int*   ei_l    = (const int*)d_in[1];
    const float* w_l     = (const float*)d_in[2];
    const float* x_s     = (const float*)d_in[3];
    const int*   ei_s    = (const int*)d_in[4];
    const float* w_s     = (const float*)d_in[5];
    const int*   batch_l = (const int*)d_in[6];
    const int*   batch_s = (const int*)d_in[7];
    const float* Wa[4] = {(const float*)d_in[8],  (const float*)d_in[12],
                          (const float*)d_in[16], (const float*)d_in[20]};
    const float* ba[4] = {(const float*)d_in[9],  (const float*)d_in[13],
                          (const float*)d_in[17], (const float*)d_in[21]};
    const float* Wb[4] = {(const float*)d_in[10], (const float*)d_in[14],
                          (const float*)d_in[18], (const float*)d_in[22]};
    const float* bb[4] = {(const float*)d_in[11], (const float*)d_in[15],
                          (const float*)d_in[19], (const float*)d_in[23]};
    const float* lin1W = (const float*)d_in[24];
    const float* lin1b = (const float*)d_in[25];
    const float* lin2W = (const float*)d_in[26];
    const float* lin2b = (const float*)d_in[27];
    const float* gamma = (const float*)d_in[28];
    const float* beta  = (const float*)d_in[29];
    const float* outW  = (const float*)d_in[30];
    const float* outb  = (const float*)d_in[31];

    int El = in_sizes[2];
    int Es = in_sizes[5];
    int Nl = in_sizes[6];
    int Ns = in_sizes[7];
    int Cl = in_sizes[0] / Nl;  // 64
    int Cs = in_sizes[3] / Ns;  // 32
    const int* src_l = ei_l;
    const int* dst_l = ei_l + El;
    const int* src_s = ei_s;
    const int* dst_s = ei_s + Es;

    float *z_l, *h_l, *z_s, *h_s, *dinv_l, *dinv_s, *pool, *cnt, *m1;
    cudaGetSymbolAddress((void**)&z_l, g_z_l);
    cudaGetSymbolAddress((void**)&h_l, g_h_l);
    cudaGetSymbolAddress((void**)&z_s, g_z_s);
    cudaGetSymbolAddress((void**)&h_s, g_h_s);
    cudaGetSymbolAddress((void**)&dinv_l, g_dinv_l);
    cudaGetSymbolAddress((void**)&dinv_s, g_dinv_s);
    cudaGetSymbolAddress((void**)&pool, g_pool);
    cudaGetSymbolAddress((void**)&cnt, g_cnt);
    cudaGetSymbolAddress((void**)&m1, g_m1);

    // --- degrees / dinv (once; A_hat is layer-invariant) ---
    zero_f<<<cdiv(Nl, 256), 256>>>(dinv_l, Nl);
    zero_f<<<cdiv(Ns, 256), 256>>>(dinv_s, Ns);
    deg_accum<<<cdiv(El, 256), 256>>>(dst_l, w_l, dinv_l, El);
    deg_accum<<<cdiv(Es, 256), 256>>>(dst_s, w_s, dinv_s, Es);
    finish_dinv<<<cdiv(Nl, 256), 256>>>(dinv_l, Nl);
    finish_dinv<<<cdiv(Ns, 256), 256>>>(dinv_s, Ns);

    // --- large branch ---
    {
        // layer 0: aggregate at C=64, then GEMM 64->128
        init_z<<<cdiv((long long)Nl * Cl, 256), 256>>>(x_l, dinv_l, z_l, Nl * Cl, 6);
        long long tot = (long long)El * (Cl / 4);
        agg_edges<16><<<cdiv(tot, 256), 256>>>((const float4*)x_l, src_l, dst_l,
                                               w_l, dinv_l, z_l, tot);
        gemm_bias_relu<64><<<cdiv(Nl, 64), 128>>>(z_l, Wa[0], ba[0], h_l, Nl);
        for (int L = 1; L < 4; L++) {
            init_z<<<cdiv((long long)Nl * 128, 256), 256>>>(h_l, dinv_l, z_l, Nl * 128, 7);
            long long t2 = (long long)El * 32;
            agg_edges<32><<<cdiv(t2, 256), 256>>>((const float4*)h_l, src_l, dst_l,
                                                  w_l, dinv_l, z_l, t2);
            gemm_bias_relu<128><<<cdiv(Nl, 64), 128>>>(z_l, Wa[L], ba[L], h_l, Nl);
        }
    }
    // --- small branch ---
    {
        init_z<<<cdiv((long long)Ns * Cs, 256), 256>>>(x_s, dinv_s, z_s, Ns * Cs, 5);
        long long tot = (long long)Es * (Cs / 4);
        agg_edges<8><<<cdiv(tot, 256), 256>>>((const float4*)x_s, src_s, dst_s,
                                              w_s, dinv_s, z_s, tot);
        gemm_bias_relu<32><<<cdiv(Ns, 64), 128>>>(z_s, Wb[0], bb[0], h_s, Ns);
        for (int L = 1; L < 4; L++) {
            init_z<<<cdiv((long long)Ns * 128, 256), 256>>>(h_s, dinv_s, z_s, Ns * 128, 7);
            long long t2 = (long long)Es * 32;
            agg_edges<32><<<cdiv(t2, 256), 256>>>((const float4*)h_s, src_s, dst_s,
                                                  w_s, dinv_s, z_s, t2);
            gemm_bias_relu<128><<<cdiv(Ns, 64), 128>>>(z_s, Wb[L], bb[L], h_s, Ns);
        }
    }

    // --- global average pool over both branches ---
    zero_f<<<cdiv(NG * 128, 256), 256>>>(pool, NG * 128);
    zero_f<<<cdiv(NG, 256), 256>>>(cnt, NG);
    pool_accum<<<cdiv((long long)Nl * 32, 256), 256>>>((const float4*)h_l, batch_l,
                                                       pool, cnt, Nl);
    pool_accum<<<cdiv((long long)Ns * 32, 256), 256>>>((const float4*)h_s, batch_s,
                                                       pool, cnt, Ns);

    // --- head MLP ---
    mlp1<<<NG, 128>>>(pool, cnt, lin1W, lin1b, m1);
    mlp2<<<NG, 64>>>(m1, lin2W, lin2b, gamma, beta, outW, outb, (float*)d_out);
}

// round 3
// speedup vs baseline: 1.7294x; 1.7294x over previous
#include <cuda_runtime.h>
#include <math.h>

// ---------------------------------------------------------------------------
// GCN_trad round 1:
//   - CSR-built aggregation (no atomics in the per-layer hot loop),
//     coef = w * dinv[src] * dinv[dst] precomputed once, reused by 4 layers.
//   - 256-thread BM=128 x BN=128 register-tiled SGEMM.
// ---------------------------------------------------------------------------

#define NLMAX 100000
#define NSMAX 50000
#define ELMAX 1600000
#define ESMAX 800000
#define NG    512

__device__ __align__(256) float g_z_l[(size_t)NLMAX * 128];
__device__ __align__(256) float g_h_l[(size_t)NLMAX * 128];
__device__ __align__(256) float g_z_s[(size_t)NSMAX * 128];
__device__ __align__(256) float g_h_s[(size_t)NSMAX * 128];
__device__ __align__(256) float g_dinv_l[NLMAX];
__device__ __align__(256) float g_dinv_s[NSMAX];
__device__ __align__(256) float g_pool[NG * 128];
__device__ __align__(256) float g_gcnt[NG];
__device__ __align__(256) float g_m1[NG * 128];

__device__ __align__(256) int   g_rp_l[NLMAX + 1];
__device__ __align__(256) int   g_rp_s[NSMAX + 1];
__device__ __align__(256) int   g_cnts_l[NLMAX];
__device__ __align__(256) int   g_cnts_s[NSMAX];
__device__ __align__(256) int   g_bsums[1024];
__device__ __align__(256) int   g_ssrc_l[ELMAX];
__device__ __align__(256) float g_coef_l[ELMAX];
__device__ __align__(256) int   g_ssrc_s[ESMAX];
__device__ __align__(256) float g_coef_s[ESMAX];

// ---------------------------------------------------------------------------

__global__ void zero_f(float* __restrict__ p, int n) {
    int i = blockIdx.x * blockDim.x + threadIdx.x;
    if (i < n) p[i] = 0.f;
}
__global__ void zero_i(int* __restrict__ p, int n) {
    int i = blockIdx.x * blockDim.x + threadIdx.x;
    if (i < n) p[i] = 0;
}
__global__ void copy_i(const int* __restrict__ a, int* __restrict__ b, int n) {
    int i = blockIdx.x * blockDim.x + threadIdx.x;
    if (i < n) b[i] = a[i];
}

__global__ void deg_accum(const int* __restrict__ dst, const float* __restrict__ w,
                          float* __restrict__ deg, int E) {
    int e = blockIdx.x * blockDim.x + threadIdx.x;
    if (e < E) atomicAdd(&deg[dst[e]], w[e]);
}
__global__ void finish_dinv(float* __restrict__ d, int n) {
    int i = blockIdx.x * blockDim.x + threadIdx.x;
    if (i < n) d[i] = rsqrtf(1.0f + d[i]);
}

// --- CSR build -------------------------------------------------------------

__global__ void hist_dst(const int* __restrict__ dst, int* __restrict__ cnt, int E) {
    int e = blockIdx.x * blockDim.x + threadIdx.x;
    if (e < E) atomicAdd(&cnt[dst[e]], 1);
}

// inclusive scan of 1024-tiles; out[i+1] = prefix_incl(in[i]); bsums[b] = tile sum
__global__ void scan_tiles(const int* __restrict__ in, int* __restrict__ out,
                           int* __restrict__ bsums, int n) {
    __shared__ int sh[1024];
    int tid = threadIdx.x;
    int i = blockIdx.x * 1024 + tid;
    int v = (i < n) ? in[i] : 0;
    sh[tid] = v;
    __syncthreads();
#pragma unroll
    for (int off = 1; off < 1024; off <<= 1) {
        int t = (tid >= off) ? sh[tid - off] : 0;
        __syncthreads();
        sh[tid] += t;
        __syncthreads();
    }
    if (i < n) out[i + 1] = sh[tid];
    if (tid == 1023) bsums[blockIdx.x] = sh[1023];
}

__global__ void scan_sums(int* __restrict__ bsums, int nb) {
    __shared__ int sh[1024];
    int tid = threadIdx.x;
    sh[tid] = (tid < nb) ? bsums[tid] : 0;
    __syncthreads();
#pragma unroll
    for (int off = 1; off < 1024; off <<= 1) {
        int t = (tid >= off) ? sh[tid - off] : 0;
        __syncthreads();
        sh[tid] += t;
        __syncthreads();
    }
    if (tid < nb) bsums[tid] = sh[tid];
}

__global__ void scan_add(int* __restrict__ out, const int* __restrict__ bsums, int n) {
    int i = blockIdx.x * blockDim.x + threadIdx.x;
    if (i == 0) out[0] = 0;
    if (i < n) {
        int b = i >> 10;
        if (b > 0) out[i + 1] += bsums[b - 1];
    }
}

__global__ void scatter_edges(const int* __restrict__ src, const int* __restrict__ dst,
                              const float* __restrict__ w, const float* __restrict__ dinv,
                              int* __restrict__ off, int* __restrict__ ssrc,
                              float* __restrict__ coef, int E) {
    int e = blockIdx.x * blockDim.x + threadIdx.x;
    if (e >= E) return;
    int s = src[e], d = dst[e];
    int p = atomicAdd(&off[d], 1);
    ssrc[p] = s;
    coef[p] = w[e] * __ldg(&dinv[s]) * __ldg(&dinv[d]);
}

// --- vector helpers --------------------------------------------------------

__device__ __forceinline__ float4 vscale(float4 v, float c) {
    return make_float4(v.x * c, v.y * c, v.z * c, v.w * c);
}
__device__ __forceinline__ float2 vscale(float2 v, float c) {
    return make_float2(v.x * c, v.y * c);
}
__device__ __forceinline__ float vscale(float v, float c) { return v * c; }
__device__ __forceinline__ float4 vfma(float4 a, float c, float4 v) {
    return make_float4(fmaf(c, v.x, a.x), fmaf(c, v.y, a.y),
                       fmaf(c, v.z, a.z), fmaf(c, v.w, a.w));
}
__device__ __forceinline__ float2 vfma(float2 a, float c, float2 v) {
    return make_float2(fmaf(c, v.x, a.x), fmaf(c, v.y, a.y));
}
__device__ __forceinline__ float vfma(float a, float c, float v) { return fmaf(c, v, a); }

// --- CSR aggregation: warp per destination row, register accumulation ------
// Node row = 32 lanes * sizeof(VT) floats; in all configs stride is 32 VT/node.
template <typename VT>
__global__ __launch_bounds__(256) void agg_csr(
    const VT* __restrict__ h, const int* __restrict__ rowptr,
    const int* __restrict__ ssrc, const float* __restrict__ coef,
    const float* __restrict__ dinv, VT* __restrict__ z, int N) {
    int wgid = (blockIdx.x * blockDim.x + threadIdx.x) >> 5;
    int lane = threadIdx.x & 31;
    if (wgid >= N) return;
    float di = __ldg(&dinv[wgid]);
    VT acc = vscale(h[(size_t)wgid * 32 + lane], di * di);
    int e = __ldg(&rowptr[wgid]);
    int e1 = __ldg(&rowptr[wgid + 1]);
    for (; e + 1 < e1; e += 2) {
        int s0 = __ldg(&ssrc[e]);
        int s1 = __ldg(&ssrc[e + 1]);
        float c0 = __ldg(&coef[e]);
        float c1 = __ldg(&coef[e + 1]);
        VT v0 = h[(size_t)s0 * 32 + lane];
        VT v1 = h[(size_t)s1 * 32 + lane];
        acc = vfma(acc, c0, v0);
        acc = vfma(acc, c1, v1);
    }
    if (e < e1) {
        int s0 = __ldg(&ssrc[e]);
        float c0 = __ldg(&coef[e]);
        acc = vfma(acc, c0, h[(size_t)s0 * 32 + lane]);
    }
    z[(size_t)wgid * 32 + lane] = acc;
}

// --- SGEMM: H = relu(Z @ W + bias), Z:[N,K], W:[K,128] ---------------------
template <int K>
__global__ __launch_bounds__(256) void gemm_bias_relu(
    const float* __restrict__ Z, const float* __restrict__ W,
    const float* __restrict__ bias, float* __restrict__ H, int N) {
    const int BM = 128, BK = 16;
    __shared__ __align__(16) float Zs[BK][BM + 4];
    __shared__ __align__(16) float Ws[BK][128];

    int tid = threadIdx.x;
    int row0 = blockIdx.x * BM;
    int tx = tid & 15;   // 16 col groups of 8
    int ty = tid >> 4;   // 16 row groups of 8

    float acc[8][8];
#pragma unroll
    for (int i = 0; i < 8; i++)
#pragma unroll
        for (int j = 0; j < 8; j++) acc[i][j] = 0.f;

    int zr = tid >> 1;           // 0..127
    int zc = (tid & 1) * 8;      // 0 or 8
    int wr = tid >> 4;           // 0..15
    int wcol = (tid & 15) * 8;   // 0..120

    for (int k0 = 0; k0 < K; k0 += BK) {
        float4 a0 = make_float4(0.f, 0.f, 0.f, 0.f), a1 = a0;
        int grow = row0 + zr;
        if (grow < N) {
            const float4* zp = (const float4*)(Z + (size_t)grow * K + k0 + zc);
            a0 = zp[0];
            a1 = zp[1];
        }
        Zs[zc + 0][zr] = a0.x; Zs[zc + 1][zr] = a0.y;
        Zs[zc + 2][zr] = a0.z; Zs[zc + 3][zr] = a0.w;
        Zs[zc + 4][zr] = a1.x; Zs[zc + 5][zr] = a1.y;
        Zs[zc + 6][zr] = a1.z; Zs[zc + 7][zr] = a1.w;
        *(float4*)&Ws[wr][wcol]     = *(const float4*)(W + (size_t)(k0 + wr) * 128 + wcol);
        *(float4*)&Ws[wr][wcol + 4] = *(const float4*)(W + (size_t)(k0 + wr) * 128 + wcol + 4);
        __syncthreads();
#pragma unroll
        for (int k = 0; k < BK; k++) {
            float a[8], b[8];
            *(float4*)&a[0] = *(const float4*)&Zs[k][ty * 8];
            *(float4*)&a[4] = *(const float4*)&Zs[k][ty * 8 + 4];
            *(float4*)&b[0] = *(const float4*)&Ws[k][tx * 8];
            *(float4*)&b[4] = *(const float4*)&Ws[k][tx * 8 + 4];
#pragma unroll
            for (int i = 0; i < 8; i++)
#pragma unroll
                for (int j = 0; j < 8; j++) acc[i][j] = fmaf(a[i], b[j], acc[i][j]);
        }
        __syncthreads();
    }

    float bv[8];
    *(float4*)&bv[0] = *(const float4*)&bias[tx * 8];
    *(float4*)&bv[4] = *(const float4*)&bias[tx * 8 + 4];
#pragma unroll
    for (int i = 0; i < 8; i++) {
        int r = row0 + ty * 8 + i;
        if (r < N) {
            float4 o0, o1;
            o0.x = fmaxf(acc[i][0] + bv[0], 0.f);
            o0.y = fmaxf(acc[i][1] + bv[1], 0.f);
            o0.z = fmaxf(acc[i][2] + bv[2], 0.f);
            o0.w = fmaxf(acc[i][3] + bv[3], 0.f);
            o1.x = fmaxf(acc[i][4] + bv[4], 0.f);
            o1.y = fmaxf(acc[i][5] + bv[5], 0.f);
            o1.z = fmaxf(acc[i][6] + bv[6], 0.f);
            o1.w = fmaxf(acc[i][7] + bv[7], 0.f);
            *(float4*)(H + (size_t)r * 128 + tx * 8) = o0;
            *(float4*)(H + (size_t)r * 128 + tx * 8 + 4) = o1;
        }
    }
}

// --- pooling + head MLP ----------------------------------------------------

__global__ void pool_accum(const float4* __restrict__ h4, const int* __restrict__ batch,
                           float* __restrict__ pool, float* __restrict__ cnt, int N) {
    int idx = blockIdx.x * blockDim.x + threadIdx.x;
    int i = idx >> 5;
    int c = idx & 31;
    if (i >= N) return;
    int b = __ldg(&batch[i]);
    float4 v = h4[(size_t)i * 32 + c];
    float* p = pool + (size_t)b * 128 + c * 4;
    asm volatile("red.global.add.v4.f32 [%0], {%1,%2,%3,%4};"
                 :: "l"(p), "f"(v.x), "f"(v.y), "f"(v.z), "f"(v.w)
                 : "memory");
    if (c == 0) atomicAdd(&cnt[b], 1.0f);
}

__global__ void mlp1(const float* __restrict__ pool, const float* __restrict__ cnt,
                     const float* __restrict__ W, const float* __restrict__ b,
                     float* __restrict__ out) {
    __shared__ float p[128];
    int g = blockIdx.x, j = threadIdx.x;
    float c = cnt[g];
    c = (c < 1.f) ? 1.f : c;
    p[j] = pool[(size_t)g * 128 + j] / c;
    __syncthreads();
    float acc = b[j];
#pragma unroll
    for (int k = 0; k < 128; k++) acc += p[k] * W[(size_t)k * 128 + j];
    out[(size_t)g * 128 + j] = acc;
}

__global__ void mlp2(const float* __restrict__ m1, const float* __restrict__ W2,
                     const float* __restrict__ b2, const float* __restrict__ gamma,
                     const float* __restrict__ beta, const float* __restrict__ outW,
                     const float* __restrict__ outb, float* __restrict__ dout) {
    __shared__ float p[128];
    __shared__ float hred[64];
    int g = blockIdx.x, j = threadIdx.x;  // 64 threads
    p[j] = m1[(size_t)g * 128 + j];
    p[j + 64] = m1[(size_t)g * 128 + 64 + j];
    __syncthreads();
    float acc = b2[j];
#pragma unroll
    for (int k = 0; k < 128; k++) acc += p[k] * W2[(size_t)k * 64 + j];
    float h = acc * rsqrtf(1.0f + 1e-5f) * gamma[j] + beta[j];
    h = fmaxf(h, 0.f);
    dout[NG + (size_t)g * 64 + j] = h;
    hred[j] = h * outW[j];
    __syncthreads();
#pragma unroll
    for (int off = 32; off >= 1; off >>= 1) {
        if (j < off) hred[j] += hred[j + off];
        __syncthreads();
    }
    if (j == 0) dout[g] = hred[0] + outb[0];
}

// ---------------------------------------------------------------------------

static inline int cdiv(long long n, int t) { return (int)((n + t - 1) / t); }

static void build_csr(const int* src, const int* dst, const float* w,
                      const float* dinv, int* cnts, int* rowptr, int* bsums,
                      int* ssrc, float* coef, int N, int E) {
    zero_i<<<cdiv(N, 256), 256>>>(cnts, N);
    hist_dst<<<cdiv(E, 256), 256>>>(dst, cnts, E);
    int nb = cdiv(N, 1024);
    scan_tiles<<<nb, 1024>>>(cnts, rowptr, bsums, N);
    scan_sums<<<1, 1024>>>(bsums, nb);
    scan_add<<<nb, 1024>>>(rowptr, bsums, N);
    copy_i<<<cdiv(N, 256), 256>>>(rowptr, cnts, N);  // running offsets
    scatter_edges<<<cdiv(E, 256), 256>>>(src, dst, w, dinv, cnts, ssrc, coef, E);
}

extern "C" void kernel_launch(void* const* d_in, const int* in_sizes, int n_in,
                              void* d_out, int out_size) {
    const float* x_l     = (const float*)d_in[0];
    const int*   ei_l    = (const int*)d_in[1];
    const float* w_l     = (const float*)d_in[2];
    const float* x_s     = (const float*)d_in[3];
    const int*   ei_s    = (const int*)d_in[4];
    const float* w_s     = (const float*)d_in[5];
    const int*   batch_l = (const int*)d_in[6];
    const int*   batch_s = (const int*)d_in[7];
    const float* Wa[4] = {(const float*)d_in[8],  (const float*)d_in[12],
                          (const float*)d_in[16], (const float*)d_in[20]};
    const float* ba[4] = {(const float*)d_in[9],  (const float*)d_in[13],
                          (const float*)d_in[17], (const float*)d_in[21]};
    const float* Wb[4] = {(const float*)d_in[10], (const float*)d_in[14],
                          (const float*)d_in[18], (const float*)d_in[22]};
    const float* bb[4] = {(const float*)d_in[11], (const float*)d_in[15],
                          (const float*)d_in[19], (const float*)d_in[23]};
    const float* lin1W = (const float*)d_in[24];
    const float* lin1b = (const float*)d_in[25];
    const float* lin2W = (const float*)d_in[26];
    const float* lin2b = (const float*)d_in[27];
    const float* gamma = (const float*)d_in[28];
    const float* beta  = (const float*)d_in[29];
    const float* outW  = (const float*)d_in[30];
    const float* outb  = (const float*)d_in[31];

    int El = in_sizes[2];
    int Es = in_sizes[5];
    int Nl = in_sizes[6];
    int Ns = in_sizes[7];
    const int* src_l = ei_l;
    const int* dst_l = ei_l + El;
    const int* src_s = ei_s;
    const int* dst_s = ei_s + Es;

    float *z_l, *h_l, *z_s, *h_s, *dinv_l, *dinv_s, *pool, *gcnt, *m1, *coef_l, *coef_s;
    int *rp_l, *rp_s, *cnts_l, *cnts_s, *bsums, *ssrc_l, *ssrc_s;
    cudaGetSymbolAddress((void**)&z_l, g_z_l);
    cudaGetSymbolAddress((void**)&h_l, g_h_l);
    cudaGetSymbolAddress((void**)&z_s, g_z_s);
    cudaGetSymbolAddress((void**)&h_s, g_h_s);
    cudaGetSymbolAddress((void**)&dinv_l, g_dinv_l);
    cudaGetSymbolAddress((void**)&dinv_s, g_dinv_s);
    cudaGetSymbolAddress((void**)&pool, g_pool);
    cudaGetSymbolAddress((void**)&gcnt, g_gcnt);
    cudaGetSymbolAddress((void**)&m1, g_m1);
    cudaGetSymbolAddress((void**)&rp_l, g_rp_l);
    cudaGetSymbolAddress((void**)&rp_s, g_rp_s);
    cudaGetSymbolAddress((void**)&cnts_l, g_cnts_l);
    cudaGetSymbolAddress((void**)&cnts_s, g_cnts_s);
    cudaGetSymbolAddress((void**)&bsums, g_bsums);
    cudaGetSymbolAddress((void**)&ssrc_l, g_ssrc_l);
    cudaGetSymbolAddress((void**)&coef_l, g_coef_l);
    cudaGetSymbolAddress((void**)&ssrc_s, g_ssrc_s);
    cudaGetSymbolAddress((void**)&coef_s, g_coef_s);

    // --- dinv (layer-invariant) ---
    zero_f<<<cdiv(Nl, 256), 256>>>(dinv_l, Nl);
    zero_f<<<cdiv(Ns, 256), 256>>>(dinv_s, Ns);
    deg_accum<<<cdiv(El, 256), 256>>>(dst_l, w_l, dinv_l, El);
    deg_accum<<<cdiv(Es, 256), 256>>>(dst_s, w_s, dinv_s, Es);
    finish_dinv<<<cdiv(Nl, 256), 256>>>(dinv_l, Nl);
    finish_dinv<<<cdiv(Ns, 256), 256>>>(dinv_s, Ns);

    // --- CSR (built once, reused by all 4 layers of each branch) ---
    build_csr(src_l, dst_l, w_l, dinv_l, cnts_l, rp_l, bsums, ssrc_l, coef_l, Nl, El);
    build_csr(src_s, dst_s, w_s, dinv_s, cnts_s, rp_s, bsums, ssrc_s, coef_s, Ns, Es);

    // --- large branch (C: 64 -> 128 -> 128 -> 128 -> 128) ---
    agg_csr<float2><<<cdiv((long long)Nl * 32, 256), 256>>>(
        (const float2*)x_l, rp_l, ssrc_l, coef_l, dinv_l, (float2*)z_l, Nl);
    gemm_bias_relu<64><<<cdiv(Nl, 128), 256>>>(z_l, Wa[0], ba[0], h_l, Nl);
    for (int L = 1; L < 4; L++) {
        agg_csr<float4><<<cdiv((long long)Nl * 32, 256), 256>>>(
            (const float4*)h_l, rp_l, ssrc_l, coef_l, dinv_l, (float4*)z_l, Nl);
        gemm_bias_relu<128><<<cdiv(Nl, 128), 256>>>(z_l, Wa[L], ba[L], h_l, Nl);
    }

    // --- small branch (C: 32 -> 128 x4) ---
    agg_csr<float><<<cdiv((long long)Ns * 32, 256), 256>>>(
        x_s, rp_s, ssrc_s, coef_s, dinv_s, z_s, Ns);
    gemm_bias_relu<32><<<cdiv(Ns, 128), 256>>>(z_s, Wb[0], bb[0], h_s, Ns);
    for (int L = 1; L < 4; L++) {
        agg_csr<float4><<<cdiv((long long)Ns * 32, 256), 256>>>(
            (const float4*)h_s, rp_s, ssrc_s, coef_s, dinv_s, (float4*)z_s, Ns);
        gemm_bias_relu<128><<<cdiv(Ns, 128), 256>>>(z_s, Wb[L], bb[L], h_s, Ns);
    }

    // --- global average pool ---
    zero_f<<<cdiv(NG * 128, 256), 256>>>(pool, NG * 128);
    zero_f<<<cdiv(NG, 256), 256>>>(gcnt, NG);
    pool_accum<<<cdiv((long long)Nl * 32, 256), 256>>>((const float4*)h_l, batch_l,
                                                       pool, gcnt, Nl);
    pool_accum<<<cdiv((long long)Ns * 32, 256), 256>>>((const float4*)h_s, batch_s,
                                                       pool, gcnt, Ns);

    // --- head MLP ---
    mlp1<<<NG, 128>>>(pool, gcnt, lin1W, lin1b, m1);
    mlp2<<<NG, 64>>>(m1, lin2W, lin2b, gamma, beta, outW, outb, (float*)d_out);
}